// round 1
// baseline (speedup 1.0000x reference)
#include <cuda_runtime.h>
#include <math.h>

// ---------------------------------------------------------------------------
// CrossAttnHead: B=16,H=12,NTAR=256,NOBS=512,D_TOT=128, 4 heads x 32
// Q decomposes: Q[b,h,t,:] = QA[b*h,:] + Qphi[t,:]  (bias+scale folded)
// ---------------------------------------------------------------------------

#define QSCALE 0.17677669529663687f   // 1/sqrt(32)

// scratch (device globals; no allocation allowed)
__device__ float g_QA[192 * 128];            // (B*H, 128), pre-scaled
__device__ float g_Qphi[256 * 128];          // (NTAR, 128), bias+scale folded
__device__ float g_Kt[16 * 4 * 32 * 512];    // [b][head][d][o]   (transposed K)
__device__ float g_V4[16 * 4 * 512 * 32];    // [b][head][o][dh]

// ---------------------------------------------------------------------------
// k1: QA = (A @ WqA^T)*s ;  Qphi = (phi @ WqB^T + bq)*s
// grid 56 blocks (8 rows each: rows 0..191 -> QA, 192..447 -> Qphi), 256 thr
// ---------------------------------------------------------------------------
__global__ __launch_bounds__(256, 1)
void k1_q(const float* __restrict__ A, const float* __restrict__ phi,
          const float* __restrict__ Wq, const float* __restrict__ bq) {
    extern __shared__ float sm[];
    float* Wqs = sm;                 // 128 x 129 (padded)
    float* Xs  = sm + 128 * 129;     // 8 x 128
    const int tid = threadIdx.x;
    const int r0  = blockIdx.x * 8;
    const bool isA = (r0 < 192);
    const int coff = isA ? 0 : 128;

    for (int g = tid; g < 128 * 128; g += 256) {
        int o = g >> 7, c = g & 127;
        Wqs[o * 129 + c] = Wq[o * 256 + coff + c];
    }
    for (int g = tid; g < 8 * 128; g += 256) {
        int r = g >> 7, c = g & 127;
        Xs[g] = isA ? A[(r0 + r) * 128 + c] : phi[(r0 - 192 + r) * 128 + c];
    }
    __syncthreads();

    const int r  = tid >> 5;        // 0..7
    const int oB = tid & 31;        // out col group
    float acc[4] = {0.f, 0.f, 0.f, 0.f};
    const float* xrow = Xs + r * 128;
    #pragma unroll 4
    for (int c = 0; c < 128; ++c) {
        float xv = xrow[c];
        #pragma unroll
        for (int m = 0; m < 4; ++m)
            acc[m] = fmaf(xv, Wqs[(oB + 32 * m) * 129 + c], acc[m]);
    }
    const int row = r0 + r;
    #pragma unroll
    for (int m = 0; m < 4; ++m) {
        int o = oB + 32 * m;
        if (isA) g_QA[row * 128 + o] = acc[m] * QSCALE;
        else     g_Qphi[(row - 192) * 128 + o] = (acc[m] + bq[o]) * QSCALE;
    }
}

// ---------------------------------------------------------------------------
// k2: K,V = H_emb_obs @ [Wk;Wv]^T + bias, written to attention-friendly layouts
// grid 256 (16 b x 8... actually 16 row-tiles of 32 rows), 256 threads
// ---------------------------------------------------------------------------
__global__ __launch_bounds__(256, 1)
void k2_kv(const float* __restrict__ X, const float* __restrict__ Wk,
           const float* __restrict__ bk, const float* __restrict__ Wv,
           const float* __restrict__ bv) {
    extern __shared__ float sm[];
    float* Ws = sm;                  // 256 x 129 (K rows then V rows)
    float* Xs = sm + 256 * 129;      // 32 x 128
    const int tid = threadIdx.x;
    const int b  = blockIdx.x >> 4;
    const int o0 = (blockIdx.x & 15) * 32;

    for (int g = tid; g < 256 * 128; g += 256) {
        int jc = g >> 7, c = g & 127;
        Ws[jc * 129 + c] = (jc < 128) ? Wk[jc * 128 + c] : Wv[(jc - 128) * 128 + c];
    }
    for (int g = tid; g < 32 * 128; g += 256)
        Xs[g] = X[(b * 512 + o0) * 128 + g];
    __syncthreads();

    const int rg = tid >> 5;   // row group: rows rg*4 .. rg*4+3
    const int cg = tid & 31;   // cols: cg + 32*m (interleaved -> conflict-free)
    float acc[4][8];
    #pragma unroll
    for (int i = 0; i < 4; ++i)
        #pragma unroll
        for (int m = 0; m < 8; ++m) acc[i][m] = 0.f;

    #pragma unroll 2
    for (int c = 0; c < 128; ++c) {
        float xv[4];
        #pragma unroll
        for (int i = 0; i < 4; ++i) xv[i] = Xs[(rg * 4 + i) * 128 + c];
        #pragma unroll
        for (int m = 0; m < 8; ++m) {
            float w = Ws[(cg + 32 * m) * 129 + c];
            #pragma unroll
            for (int i = 0; i < 4; ++i) acc[i][m] = fmaf(xv[i], w, acc[i][m]);
        }
    }
    #pragma unroll
    for (int m = 0; m < 8; ++m) {
        int jc = cg + 32 * m;
        #pragma unroll
        for (int i = 0; i < 4; ++i) {
            int o = o0 + rg * 4 + i;
            if (jc < 128) {
                int hd = jc >> 5, d = jc & 31;
                g_Kt[((b * 4 + hd) * 32 + d) * 512 + o] = acc[i][m] + bk[jc];
            } else {
                int j = jc - 128;
                int hd = j >> 5, dh = j & 31;
                g_V4[((b * 4 + hd) * 512 + o) * 32 + dh] = acc[i][m] + bv[j];
            }
        }
    }
}

// ---------------------------------------------------------------------------
// k3: fused attention (4 heads) + FFN(Linear->LN->ReLU->Linear) per 32-row tile
// grid (8 t-tiles, 192 bh), 256 threads, ~144 KB smem
// smem carve (floats):
//   SC  : 18432  scores [32][528] ; later W1^T [128][144]
//   QT  : 4096   q transposed [d_tot=128][t=32]
//   KC  : 4096   K chunk  [d=32][o=128]
//   VC  : 4608   V chunk  [o=128][dh=32 pad36]
//   CTX : 4224   context  [t=32][c=128 pad132]
//   PRM : 512    b1|ln_g|ln_b|W2
//   RED : 32     1/rowsum
// ---------------------------------------------------------------------------
#define SM3_SC   0
#define SM3_QT   18432
#define SM3_KC   22528
#define SM3_VC   26624
#define SM3_CTX  31232
#define SM3_PRM  35456
#define SM3_RED  35968
#define SM3_TOTF 36000

__global__ __launch_bounds__(256, 1)
void k3_attn_ffn(const float* __restrict__ b1, const float* __restrict__ lng,
                 const float* __restrict__ lnb, const float* __restrict__ W2,
                 const float* __restrict__ b2, const float* __restrict__ W1,
                 float* __restrict__ out) {
    extern __shared__ float sm[];
    float* SC  = sm + SM3_SC;
    float* QT  = sm + SM3_QT;
    float* KC  = sm + SM3_KC;
    float* VC  = sm + SM3_VC;
    float* CTX = sm + SM3_CTX;
    float* PRM = sm + SM3_PRM;
    float* RED = sm + SM3_RED;

    const int tid = threadIdx.x;
    const int bh  = blockIdx.y;          // 0..191
    const int b   = bh / 12;
    const int t0  = blockIdx.x * 32;

    // stage small params
    for (int g = tid; g < 512; g += 256) {
        int c = g & 127, s = g >> 7;
        float v = (s == 0) ? b1[c] : (s == 1) ? lng[c] : (s == 2) ? lnb[c] : W2[c];
        PRM[g] = v;
    }
    // build q^T: QT[dt][t] = QA[bh][dt] + Qphi[t0+t][dt]   (both pre-scaled)
    for (int g = tid; g < 4096; g += 256) {
        int t = g & 31, dt = g >> 5;
        QT[dt * 32 + t] = g_QA[bh * 128 + dt] + g_Qphi[(t0 + t) * 128 + dt];
    }

    const int tb = (tid >> 5) * 4;       // t quad (QK)
    const int ob = (tid & 31) * 4;       // o quad within chunk (QK)
    const int ta = tid >> 3;             // t (AV/FFN)
    const int db = (tid & 7) * 4;        // dh quad (AV)

    for (int hd = 0; hd < 4; ++hd) {
        const float* Kth = g_Kt + (b * 4 + hd) * 16384;
        const float* V4h = g_V4 + (b * 4 + hd) * 16384;

        // ---- scores S = q^T K (chunks of 128 obs) ----
        for (int oc = 0; oc < 4; ++oc) {
            __syncthreads();
            for (int g = tid; g < 4096; g += 256) {
                int d = g >> 7, o = g & 127;
                KC[g] = Kth[d * 512 + oc * 128 + o];   // KC[d][o]
            }
            __syncthreads();

            float acc[4][4];
            #pragma unroll
            for (int i = 0; i < 4; ++i)
                #pragma unroll
                for (int j = 0; j < 4; ++j) acc[i][j] = 0.f;

            const float* qbase = QT + (hd * 32) * 32 + tb;
            const float* kcb   = KC + ob;
            #pragma unroll 4
            for (int d = 0; d < 32; ++d) {
                float4 q = *(const float4*)(qbase + d * 32);
                float4 k = *(const float4*)(kcb + d * 128);
                acc[0][0] = fmaf(q.x, k.x, acc[0][0]);
                acc[0][1] = fmaf(q.x, k.y, acc[0][1]);
                acc[0][2] = fmaf(q.x, k.z, acc[0][2]);
                acc[0][3] = fmaf(q.x, k.w, acc[0][3]);
                acc[1][0] = fmaf(q.y, k.x, acc[1][0]);
                acc[1][1] = fmaf(q.y, k.y, acc[1][1]);
                acc[1][2] = fmaf(q.y, k.z, acc[1][2]);
                acc[1][3] = fmaf(q.y, k.w, acc[1][3]);
                acc[2][0] = fmaf(q.z, k.x, acc[2][0]);
                acc[2][1] = fmaf(q.z, k.y, acc[2][1]);
                acc[2][2] = fmaf(q.z, k.z, acc[2][2]);
                acc[2][3] = fmaf(q.z, k.w, acc[2][3]);
                acc[3][0] = fmaf(q.w, k.x, acc[3][0]);
                acc[3][1] = fmaf(q.w, k.y, acc[3][1]);
                acc[3][2] = fmaf(q.w, k.z, acc[3][2]);
                acc[3][3] = fmaf(q.w, k.w, acc[3][3]);
            }
            #pragma unroll
            for (int i = 0; i < 4; ++i)
                *(float4*)(SC + (tb + i) * 528 + oc * 128 + ob) =
                    make_float4(acc[i][0], acc[i][1], acc[i][2], acc[i][3]);
        }
        __syncthreads();

        // ---- softmax over 512 per row: warp w handles rows w*4..w*4+3 ----
        {
            const int w = tid >> 5, lane = tid & 31;
            #pragma unroll
            for (int tt = 0; tt < 4; ++tt) {
                int t = w * 4 + tt;
                float* row = SC + t * 528 + lane;
                float v[16];
                float mx = -1e30f;
                #pragma unroll
                for (int k = 0; k < 16; ++k) { v[k] = row[k * 32]; mx = fmaxf(mx, v[k]); }
                #pragma unroll
                for (int off = 16; off; off >>= 1)
                    mx = fmaxf(mx, __shfl_xor_sync(0xffffffffu, mx, off));
                float s = 0.f;
                #pragma unroll
                for (int k = 0; k < 16; ++k) {
                    float e = __expf(v[k] - mx);
                    row[k * 32] = e;
                    s += e;
                }
                #pragma unroll
                for (int off = 16; off; off >>= 1)
                    s += __shfl_xor_sync(0xffffffffu, s, off);
                if (lane == 0) RED[t] = 1.f / s;
            }
        }
        __syncthreads();

        // ---- ctx = attn @ V ----
        float cx = 0.f, cy = 0.f, cz = 0.f, cw = 0.f;
        for (int oc = 0; oc < 4; ++oc) {
            __syncthreads();                    // prior VC readers done
            for (int g = tid; g < 4096; g += 256) {
                int o = g >> 5, dh = g & 31;
                VC[o * 36 + dh] = V4h[(oc * 128 + o) * 32 + dh];
            }
            __syncthreads();
            const float* scrow = SC + ta * 528 + oc * 128;
            #pragma unroll 4
            for (int o = 0; o < 128; ++o) {
                float a = scrow[o];
                float4 v = *(const float4*)(VC + o * 36 + db);
                cx = fmaf(a, v.x, cx);
                cy = fmaf(a, v.y, cy);
                cz = fmaf(a, v.z, cz);
                cw = fmaf(a, v.w, cw);
            }
        }
        float inv = RED[ta];
        *(float4*)(CTX + ta * 132 + hd * 32 + db) =
            make_float4(cx * inv, cy * inv, cz * inv, cw * inv);
    }
    __syncthreads();

    // ---- FFN: stage W1^T into SC (rows of 144), x = ctx @ W1^T + b1 ----
    for (int g = tid; g < 16384; g += 256) {
        int j = g >> 7, c = g & 127;
        SC[c * 144 + j] = W1[g];
    }
    __syncthreads();

    const int jb = (tid & 7) * 4;  // j quad base; thread covers j = jb + 32*kk + comp
    float xa[4][4];
    #pragma unroll
    for (int kk = 0; kk < 4; ++kk)
        #pragma unroll
        for (int c = 0; c < 4; ++c) xa[kk][c] = 0.f;

    const float* ctr = CTX + ta * 132;
    #pragma unroll 2
    for (int c = 0; c < 128; ++c) {
        float cv = ctr[c];
        const float* wr = SC + c * 144 + jb;
        #pragma unroll
        for (int kk = 0; kk < 4; ++kk) {
            float4 w = *(const float4*)(wr + 32 * kk);
            xa[kk][0] = fmaf(cv, w.x, xa[kk][0]);
            xa[kk][1] = fmaf(cv, w.y, xa[kk][1]);
            xa[kk][2] = fmaf(cv, w.z, xa[kk][2]);
            xa[kk][3] = fmaf(cv, w.w, xa[kk][3]);
        }
    }
    // bias + LN stats (row t = ta is spread across 8 consecutive lanes)
    float sum = 0.f, sq = 0.f;
    #pragma unroll
    for (int kk = 0; kk < 4; ++kk)
        #pragma unroll
        for (int c = 0; c < 4; ++c) {
            int j = jb + 32 * kk + c;
            float x = xa[kk][c] + PRM[j];
            xa[kk][c] = x;
            sum += x;
            sq  = fmaf(x, x, sq);
        }
    #pragma unroll
    for (int off = 1; off < 8; off <<= 1) {
        sum += __shfl_xor_sync(0xffffffffu, sum, off);
        sq  += __shfl_xor_sync(0xffffffffu, sq, off);
    }
    float mu   = sum * (1.f / 128.f);
    float var  = sq * (1.f / 128.f) - mu * mu;
    float rstd = rsqrtf(var + 1e-5f);

    float yv = 0.f;
    #pragma unroll
    for (int kk = 0; kk < 4; ++kk)
        #pragma unroll
        for (int c = 0; c < 4; ++c) {
            int j = jb + 32 * kk + c;
            float xn = (xa[kk][c] - mu) * rstd * PRM[128 + j] + PRM[256 + j];
            xn = fmaxf(xn, 0.f);
            yv = fmaf(xn, PRM[384 + j], yv);
        }
    #pragma unroll
    for (int off = 1; off < 8; off <<= 1)
        yv += __shfl_xor_sync(0xffffffffu, yv, off);

    if ((tid & 7) == 0)
        out[bh * 256 + t0 + ta] = yv + b2[0];
}

// ---------------------------------------------------------------------------
extern "C" void kernel_launch(void* const* d_in, const int* in_sizes, int n_in,
                              void* d_out, int out_size) {
    const float* A   = (const float*)d_in[0];
    const float* phi = (const float*)d_in[1];
    const float* X   = (const float*)d_in[2];
    const float* Wq  = (const float*)d_in[3];
    const float* bq  = (const float*)d_in[4];
    const float* Wk  = (const float*)d_in[5];
    const float* bk  = (const float*)d_in[6];
    const float* Wv  = (const float*)d_in[7];
    const float* bv  = (const float*)d_in[8];
    const float* W1  = (const float*)d_in[9];
    const float* b1  = (const float*)d_in[10];
    const float* lng = (const float*)d_in[11];
    const float* lnb = (const float*)d_in[12];
    const float* W2  = (const float*)d_in[13];
    const float* b2  = (const float*)d_in[14];
    float* out = (float*)d_out;

    const int smem1 = (128 * 129 + 8 * 128) * 4;    // 70144
    const int smem2 = (256 * 129 + 32 * 128) * 4;   // 148480
    const int smem3 = SM3_TOTF * 4;                 // 144000

    cudaFuncSetAttribute(k1_q, cudaFuncAttributeMaxDynamicSharedMemorySize, smem1);
    cudaFuncSetAttribute(k2_kv, cudaFuncAttributeMaxDynamicSharedMemorySize, smem2);
    cudaFuncSetAttribute(k3_attn_ffn, cudaFuncAttributeMaxDynamicSharedMemorySize, smem3);

    k1_q<<<56, 256, smem1>>>(A, phi, Wq, bq);
    k2_kv<<<256, 256, smem2>>>(X, Wk, bk, Wv, bv);

    dim3 grid3(8, 192);
    k3_attn_ffn<<<grid3, 256, smem3>>>(b1, lng, lnb, W2, b2, W1, out);
}

// round 2
// speedup vs baseline: 1.6553x; 1.6553x over previous
#include <cuda_runtime.h>
#include <math.h>

// ---------------------------------------------------------------------------
// CrossAttnHead: B=16,H=12,NTAR=256,NOBS=512,D_TOT=128, 4 heads x 32
// Q decomposes: Q[b,h,t,:] = QA[b*h,:] + Qphi[t,:]  (bias+scale folded)
// ---------------------------------------------------------------------------

#define QSCALE 0.17677669529663687f   // 1/sqrt(32)

__device__ float g_QA[192 * 128];            // (B*H, 128), pre-scaled
__device__ float g_Qphi[256 * 128];          // (NTAR, 128), bias+scale folded
__device__ float g_Kt[16 * 4 * 32 * 512];    // [b][head][d][o]   (transposed K)
__device__ float g_V4[16 * 4 * 512 * 32];    // [b][head][o][dh]

// ---------------------------------------------------------------------------
// k1: QA = (A @ WqA^T)*s ;  Qphi = (phi @ WqB^T + bq)*s
// ---------------------------------------------------------------------------
__global__ __launch_bounds__(256, 1)
void k1_q(const float* __restrict__ A, const float* __restrict__ phi,
          const float* __restrict__ Wq, const float* __restrict__ bq) {
    extern __shared__ float sm[];
    float* Wqs = sm;                 // 128 x 129
    float* Xs  = sm + 128 * 129;     // 8 x 128
    const int tid = threadIdx.x;
    const int r0  = blockIdx.x * 8;
    const bool isA = (r0 < 192);
    const int coff = isA ? 0 : 128;

    for (int g = tid; g < 128 * 128; g += 256) {
        int o = g >> 7, c = g & 127;
        Wqs[o * 129 + c] = Wq[o * 256 + coff + c];
    }
    for (int g = tid; g < 8 * 128; g += 256) {
        int r = g >> 7, c = g & 127;
        Xs[g] = isA ? A[(r0 + r) * 128 + c] : phi[(r0 - 192 + r) * 128 + c];
    }
    __syncthreads();

    const int r  = tid >> 5;
    const int oB = tid & 31;
    float acc[4] = {0.f, 0.f, 0.f, 0.f};
    const float* xrow = Xs + r * 128;
    #pragma unroll 4
    for (int c = 0; c < 128; ++c) {
        float xv = xrow[c];
        #pragma unroll
        for (int m = 0; m < 4; ++m)
            acc[m] = fmaf(xv, Wqs[(oB + 32 * m) * 129 + c], acc[m]);
    }
    const int row = r0 + r;
    #pragma unroll
    for (int m = 0; m < 4; ++m) {
        int o = oB + 32 * m;
        if (isA) g_QA[row * 128 + o] = acc[m] * QSCALE;
        else     g_Qphi[(row - 192) * 128 + o] = (acc[m] + bq[o]) * QSCALE;
    }
}

// ---------------------------------------------------------------------------
// k2: K,V = H_emb_obs @ [Wk;Wv]^T + bias -> attention-friendly layouts
// ---------------------------------------------------------------------------
__global__ __launch_bounds__(256, 1)
void k2_kv(const float* __restrict__ X, const float* __restrict__ Wk,
           const float* __restrict__ bk, const float* __restrict__ Wv,
           const float* __restrict__ bv) {
    extern __shared__ float sm[];
    float* Ws = sm;                  // 256 x 129
    float* Xs = sm + 256 * 129;      // 32 x 128
    const int tid = threadIdx.x;
    const int b  = blockIdx.x >> 4;
    const int o0 = (blockIdx.x & 15) * 32;

    for (int g = tid; g < 256 * 128; g += 256) {
        int jc = g >> 7, c = g & 127;
        Ws[jc * 129 + c] = (jc < 128) ? Wk[jc * 128 + c] : Wv[(jc - 128) * 128 + c];
    }
    for (int g = tid; g < 32 * 128; g += 256)
        Xs[g] = X[(b * 512 + o0) * 128 + g];
    __syncthreads();

    const int rg = tid >> 5;
    const int cg = tid & 31;
    float acc[4][8];
    #pragma unroll
    for (int i = 0; i < 4; ++i)
        #pragma unroll
        for (int m = 0; m < 8; ++m) acc[i][m] = 0.f;

    #pragma unroll 2
    for (int c = 0; c < 128; ++c) {
        float xv[4];
        #pragma unroll
        for (int i = 0; i < 4; ++i) xv[i] = Xs[(rg * 4 + i) * 128 + c];
        #pragma unroll
        for (int m = 0; m < 8; ++m) {
            float w = Ws[(cg + 32 * m) * 129 + c];
            #pragma unroll
            for (int i = 0; i < 4; ++i) acc[i][m] = fmaf(xv[i], w, acc[i][m]);
        }
    }
    #pragma unroll
    for (int m = 0; m < 8; ++m) {
        int jc = cg + 32 * m;
        #pragma unroll
        for (int i = 0; i < 4; ++i) {
            int o = o0 + rg * 4 + i;
            if (jc < 128) {
                int hd = jc >> 5, d = jc & 31;
                g_Kt[((b * 4 + hd) * 32 + d) * 512 + o] = acc[i][m] + bk[jc];
            } else {
                int j = jc - 128;
                int hd = j >> 5, dh = j & 31;
                g_V4[((b * 4 + hd) * 512 + o) * 32 + dh] = acc[i][m] + bv[j];
            }
        }
    }
}

// ---------------------------------------------------------------------------
// k3: fused attention (4 heads) + FFN per 32-t-row tile; 512 threads
// smem carve (floats):
//   SC  : 16896  scores [32][516] ; later W1^T [128][132]
//   QT  : 4096   q^T [128][32]
//   KC  : 8192   K chunk pair [2][32][128]
//   VC  : 9216   V chunk pair [2][128][36] ; aliased as PART [8][32][36]
//   CTX : 4224   context [32][132]
//   PRM : 512    b1|ln_g|ln_b|W2
//   RED : 32
// ---------------------------------------------------------------------------
#define SM_SC   0
#define SM_QT   16896
#define SM_KC   20992
#define SM_VC   29184
#define SM_CTX  38400
#define SM_PRM  42624
#define SM_RED  43136
#define SM_TOTF 43168
#define SCS     516

__global__ __launch_bounds__(512, 1)
void k3_attn_ffn(const float* __restrict__ b1, const float* __restrict__ lng,
                 const float* __restrict__ lnb, const float* __restrict__ W2,
                 const float* __restrict__ b2, const float* __restrict__ W1,
                 float* __restrict__ out) {
    extern __shared__ float sm[];
    float* SC  = sm + SM_SC;
    float* QT  = sm + SM_QT;
    float* KC  = sm + SM_KC;
    float* VC  = sm + SM_VC;
    float* CTX = sm + SM_CTX;
    float* PRM = sm + SM_PRM;
    float* RED = sm + SM_RED;

    const int tid = threadIdx.x;
    const int bh  = blockIdx.y;          // 0..191
    const int b   = bh / 12;
    const int t0  = blockIdx.x * 32;

    // small params
    {
        int c = tid & 127, s = tid >> 7;
        float v = (s == 0) ? b1[c] : (s == 1) ? lng[c] : (s == 2) ? lnb[c] : W2[c];
        PRM[tid] = v;
    }
    // q^T
    for (int g = tid; g < 4096; g += 512) {
        int t = g & 31, dt = g >> 5;
        QT[dt * 32 + t] = g_QA[bh * 128 + dt] + g_Qphi[(t0 + t) * 128 + dt];
    }

    const int half = tid >> 8;               // chunk selector within pair
    const int t256 = tid & 255;
    const int tbq  = (t256 >> 5) * 4;        // QK: t quad
    const int obq  = (t256 & 31) * 4;        // QK: o quad
    const int w    = tid >> 5, lane = tid & 31;   // softmax
    const int osub = (tid >> 6) & 3;         // AV: 32-obs window within chunk
    const int tba  = ((tid >> 3) & 7) * 4;   // AV: t quad
    const int dba  = (tid & 7) * 4;          // AV: dh quad
    const int sIdx = half * 4 + osub;        // partial slot
    const int ta   = tid >> 4;               // reduce/FFN: t row
    const int m16  = tid & 15;

    for (int hd = 0; hd < 4; ++hd) {
        const float* Kth = g_Kt + (b * 4 + hd) * 16384;
        const float* V4h = g_V4 + (b * 4 + hd) * 16384;

        // ---- scores S = q^T K, chunk pairs ----
        for (int p = 0; p < 2; ++p) {
            __syncthreads();
            for (int g = tid; g < 8192; g += 512) {
                int ch = g >> 12, d = (g >> 7) & 31, o = g & 127;
                KC[g] = Kth[d * 512 + (p * 2 + ch) * 128 + o];
            }
            __syncthreads();

            float acc[4][4];
            #pragma unroll
            for (int i = 0; i < 4; ++i)
                #pragma unroll
                for (int j = 0; j < 4; ++j) acc[i][j] = 0.f;

            const float* qb = QT + hd * 1024 + tbq;
            const float* kb = KC + half * 4096 + obq;
            #pragma unroll 4
            for (int d = 0; d < 32; ++d) {
                float4 q = *(const float4*)(qb + d * 32);
                float4 k = *(const float4*)(kb + d * 128);
                acc[0][0] = fmaf(q.x, k.x, acc[0][0]);
                acc[0][1] = fmaf(q.x, k.y, acc[0][1]);
                acc[0][2] = fmaf(q.x, k.z, acc[0][2]);
                acc[0][3] = fmaf(q.x, k.w, acc[0][3]);
                acc[1][0] = fmaf(q.y, k.x, acc[1][0]);
                acc[1][1] = fmaf(q.y, k.y, acc[1][1]);
                acc[1][2] = fmaf(q.y, k.z, acc[1][2]);
                acc[1][3] = fmaf(q.y, k.w, acc[1][3]);
                acc[2][0] = fmaf(q.z, k.x, acc[2][0]);
                acc[2][1] = fmaf(q.z, k.y, acc[2][1]);
                acc[2][2] = fmaf(q.z, k.z, acc[2][2]);
                acc[2][3] = fmaf(q.z, k.w, acc[2][3]);
                acc[3][0] = fmaf(q.w, k.x, acc[3][0]);
                acc[3][1] = fmaf(q.w, k.y, acc[3][1]);
                acc[3][2] = fmaf(q.w, k.z, acc[3][2]);
                acc[3][3] = fmaf(q.w, k.w, acc[3][3]);
            }
            const int col = (p * 2 + half) * 128 + obq;
            #pragma unroll
            for (int i = 0; i < 4; ++i)
                *(float4*)(SC + (tbq + i) * SCS + col) =
                    make_float4(acc[i][0], acc[i][1], acc[i][2], acc[i][3]);
        }
        __syncthreads();

        // ---- softmax: warp w handles rows 2w, 2w+1 ----
        #pragma unroll
        for (int tt = 0; tt < 2; ++tt) {
            int t = w * 2 + tt;
            float* row = SC + t * SCS + lane;
            float v[16];
            float mx = -1e30f;
            #pragma unroll
            for (int k = 0; k < 16; ++k) { v[k] = row[k * 32]; mx = fmaxf(mx, v[k]); }
            #pragma unroll
            for (int off = 16; off; off >>= 1)
                mx = fmaxf(mx, __shfl_xor_sync(0xffffffffu, mx, off));
            float s = 0.f;
            #pragma unroll
            for (int k = 0; k < 16; ++k) {
                float e = __expf(v[k] - mx);
                row[k * 32] = e;
                s += e;
            }
            #pragma unroll
            for (int off = 16; off; off >>= 1)
                s += __shfl_xor_sync(0xffffffffu, s, off);
            if (lane == 0) RED[t] = 1.f / s;
        }

        // ---- ctx partial = attn @ V (4x4 register tile, 8-way o-split) ----
        float av[4][4];
        #pragma unroll
        for (int i = 0; i < 4; ++i)
            #pragma unroll
            for (int j = 0; j < 4; ++j) av[i][j] = 0.f;

        for (int p = 0; p < 2; ++p) {
            __syncthreads();
            for (int g = tid; g < 8192; g += 512) {
                int ch = g >> 12, o = (g >> 5) & 127, dh = g & 31;
                VC[ch * 4608 + o * 36 + dh] = V4h[((p * 2 + ch) * 128 + o) * 32 + dh];
            }
            __syncthreads();

            const int colbase = (p * 2 + half) * 128 + osub * 32;
            const float* vb = VC + half * 4608 + osub * 32 * 36 + dba;
            #pragma unroll
            for (int q8 = 0; q8 < 8; ++q8) {
                const int o4 = q8 * 4;
                float4 a[4], v[4];
                #pragma unroll
                for (int i = 0; i < 4; ++i)
                    a[i] = *(const float4*)(SC + (tba + i) * SCS + colbase + o4);
                #pragma unroll
                for (int j = 0; j < 4; ++j)
                    v[j] = *(const float4*)(vb + (o4 + j) * 36);
                #pragma unroll
                for (int oo = 0; oo < 4; ++oo) {
                    float4 vv = v[oo];
                    #pragma unroll
                    for (int i = 0; i < 4; ++i) {
                        float s = reinterpret_cast<const float*>(&a[i])[oo];
                        av[i][0] = fmaf(s, vv.x, av[i][0]);
                        av[i][1] = fmaf(s, vv.y, av[i][1]);
                        av[i][2] = fmaf(s, vv.z, av[i][2]);
                        av[i][3] = fmaf(s, vv.w, av[i][3]);
                    }
                }
            }
        }

        // ---- reduce 8 partials per output, scale by 1/rowsum ----
        __syncthreads();                       // VC readers done (alias below)
        float* PART = VC;
        #pragma unroll
        for (int i = 0; i < 4; ++i)
            *(float4*)(PART + sIdx * 1152 + (tba + i) * 36 + dba) =
                make_float4(av[i][0], av[i][1], av[i][2], av[i][3]);
        __syncthreads();

        float rx = 0.f, ry = 0.f;
        #pragma unroll
        for (int s = 0; s < 8; ++s) {
            float2 t2 = *(const float2*)(PART + s * 1152 + ta * 36 + m16 * 2);
            rx += t2.x; ry += t2.y;
        }
        float inv = RED[ta];
        CTX[ta * 132 + hd * 32 + m16 * 2]     = rx * inv;
        CTX[ta * 132 + hd * 32 + m16 * 2 + 1] = ry * inv;
    }

    // ---- FFN: x = ctx @ W1^T + b1 -> LN -> ReLU -> dot(W2) ----
    __syncthreads();
    for (int g = tid; g < 16384; g += 512) {
        int j = g >> 7, c = g & 127;
        SC[c * 132 + j] = W1[g];
    }
    __syncthreads();

    const int jb = m16 * 4;   // thread covers j = jb..jb+3 and jb+64..jb+67
    float x0[4] = {0.f, 0.f, 0.f, 0.f};
    float x1[4] = {0.f, 0.f, 0.f, 0.f};
    const float* ctr = CTX + ta * 132;
    #pragma unroll 2
    for (int c = 0; c < 128; ++c) {
        float cv = ctr[c];
        float4 w0 = *(const float4*)(SC + c * 132 + jb);
        float4 w1 = *(const float4*)(SC + c * 132 + jb + 64);
        x0[0] = fmaf(cv, w0.x, x0[0]);
        x0[1] = fmaf(cv, w0.y, x0[1]);
        x0[2] = fmaf(cv, w0.z, x0[2]);
        x0[3] = fmaf(cv, w0.w, x0[3]);
        x1[0] = fmaf(cv, w1.x, x1[0]);
        x1[1] = fmaf(cv, w1.y, x1[1]);
        x1[2] = fmaf(cv, w1.z, x1[2]);
        x1[3] = fmaf(cv, w1.w, x1[3]);
    }
    float sum = 0.f, sq = 0.f;
    #pragma unroll
    for (int k = 0; k < 4; ++k) {
        float a = x0[k] + PRM[jb + k];
        float c2 = x1[k] + PRM[jb + 64 + k];
        x0[k] = a; x1[k] = c2;
        sum += a + c2;
        sq = fmaf(a, a, sq);
        sq = fmaf(c2, c2, sq);
    }
    #pragma unroll
    for (int off = 1; off < 16; off <<= 1) {
        sum += __shfl_xor_sync(0xffffffffu, sum, off);
        sq  += __shfl_xor_sync(0xffffffffu, sq, off);
    }
    float mu   = sum * (1.f / 128.f);
    float var  = sq * (1.f / 128.f) - mu * mu;
    float rstd = rsqrtf(var + 1e-5f);

    float yv = 0.f;
    #pragma unroll
    for (int k = 0; k < 4; ++k) {
        int j0 = jb + k, j1 = jb + 64 + k;
        float xn0 = fmaxf((x0[k] - mu) * rstd * PRM[128 + j0] + PRM[256 + j0], 0.f);
        float xn1 = fmaxf((x1[k] - mu) * rstd * PRM[128 + j1] + PRM[256 + j1], 0.f);
        yv = fmaf(xn0, PRM[384 + j0], yv);
        yv = fmaf(xn1, PRM[384 + j1], yv);
    }
    #pragma unroll
    for (int off = 1; off < 16; off <<= 1)
        yv += __shfl_xor_sync(0xffffffffu, yv, off);

    if (m16 == 0)
        out[bh * 256 + t0 + ta] = yv + b2[0];
}

// ---------------------------------------------------------------------------
extern "C" void kernel_launch(void* const* d_in, const int* in_sizes, int n_in,
                              void* d_out, int out_size) {
    const float* A   = (const float*)d_in[0];
    const float* phi = (const float*)d_in[1];
    const float* X   = (const float*)d_in[2];
    const float* Wq  = (const float*)d_in[3];
    const float* bq  = (const float*)d_in[4];
    const float* Wk  = (const float*)d_in[5];
    const float* bk  = (const float*)d_in[6];
    const float* Wv  = (const float*)d_in[7];
    const float* bv  = (const float*)d_in[8];
    const float* W1  = (const float*)d_in[9];
    const float* b1  = (const float*)d_in[10];
    const float* lng = (const float*)d_in[11];
    const float* lnb = (const float*)d_in[12];
    const float* W2  = (const float*)d_in[13];
    const float* b2  = (const float*)d_in[14];
    float* out = (float*)d_out;

    const int smem1 = (128 * 129 + 8 * 128) * 4;
    const int smem2 = (256 * 129 + 32 * 128) * 4;
    const int smem3 = SM_TOTF * 4;   // 172672

    cudaFuncSetAttribute(k1_q, cudaFuncAttributeMaxDynamicSharedMemorySize, smem1);
    cudaFuncSetAttribute(k2_kv, cudaFuncAttributeMaxDynamicSharedMemorySize, smem2);
    cudaFuncSetAttribute(k3_attn_ffn, cudaFuncAttributeMaxDynamicSharedMemorySize, smem3);

    k1_q<<<56, 256, smem1>>>(A, phi, Wq, bq);
    k2_kv<<<256, 256, smem2>>>(X, Wk, bk, Wv, bv);

    dim3 grid3(8, 192);
    k3_attn_ffn<<<grid3, 512, smem3>>>(b1, lng, lnb, W2, b2, W1, out);
}